// round 15
// baseline (speedup 1.0000x reference)
#include <cuda_runtime.h>
#include <cstdint>

// PolicyEncoder gather-sum:
// out[n, :] = bias + w_state0[obs0[n]] + w_state1[obs1[n]] + w_act0[act0[n]] + w_act1[act1[n]]
// N = 262144 rows, D = 128 floats per row.
//
// R15 = R14 kernel (consume-then-issue 2-stage pipeline, 48 regs,
// 148*5-block exact wave = 40 warps/SM, broadcast index loads, __stcs
// streaming stores) + a per-launch L2 ACCESS POLICY WINDOW over w_state0:
//  - hitProp = persisting, missProp = streaming. Unlike ld/st cache hints
//    (tried R3/R4/R7/R11, all no-ops on traffic), the window is a HW-tracked
//    address range: lines from w_state0 are retained across graph replays
//    while the 134MB/launch output stream is demoted to streaming class.
//  - Window size clamped to cudaDevAttrMaxAccessPolicyWindowSize; if the
//    device reports 0 (unsupported), fall back to a plain launch (== R14).

struct Idx { int i0, i1, i2, i3; };

__device__ __forceinline__ Idx load_idx(const int* __restrict__ o0,
                                        const int* __restrict__ o1,
                                        const int* __restrict__ a0,
                                        const int* __restrict__ a1, int r) {
    Idx x;
    x.i0 = __ldg(o0 + r);
    x.i1 = __ldg(o1 + r);
    x.i2 = __ldg(a0 + r);
    x.i3 = __ldg(a1 + r);
    return x;
}

__global__ void __launch_bounds__(256, 5)
policy_encoder_kernel(const int* __restrict__ obs0,
                      const int* __restrict__ obs1,
                      const int* __restrict__ act0,
                      const int* __restrict__ act1,
                      const float4* __restrict__ w0,   // [OBS0, 32] as float4
                      const float4* __restrict__ w1,
                      const float4* __restrict__ w2,
                      const float4* __restrict__ w3,
                      const float4* __restrict__ bias, // [32]
                      float4* __restrict__ out,        // [N, 32]
                      int n)
{
    const int lane   = threadIdx.x & 31;
    const int gw     = (int)((blockIdx.x * blockDim.x + threadIdx.x) >> 5);
    const int stride = (int)((gridDim.x * blockDim.x) >> 5);

    if (gw >= n) return;

    const float4 b = __ldg(bias + lane);
    const int last = n - 1;

    // ---- prologue ----
    Idx ic = load_idx(obs0, obs1, act0, act1, gw);
    int r1 = gw + stride;
    Idx in_ = load_idx(obs0, obs1, act0, act1, r1 <= last ? r1 : last);

    float4 g0 = __ldg(w0 + (size_t)ic.i0 * 32 + lane);
    float4 g1 = __ldg(w1 + (size_t)ic.i1 * 32 + lane);
    float4 g2 = __ldg(w2 + (size_t)ic.i2 * 32 + lane);
    float4 g3 = __ldg(w3 + (size_t)ic.i3 * 32 + lane);

    // ---- steady state: consume row r, THEN issue row r+stride into g ----
    for (int r = gw; r <= last; r += stride) {
        int rnn = r + 2 * stride;
        Idx inn = load_idx(obs0, obs1, act0, act1, rnn <= last ? rnn : last);

        float4 res;
        res.x = b.x + g0.x + g1.x + g2.x + g3.x;
        res.y = b.y + g0.y + g1.y + g2.y + g3.y;
        res.z = b.z + g0.z + g1.z + g2.z + g3.z;
        res.w = b.w + g0.w + g1.w + g2.w + g3.w;
        __stcs(out + (size_t)r * 32 + lane, res);

        g0 = __ldg(w0 + (size_t)in_.i0 * 32 + lane);
        g1 = __ldg(w1 + (size_t)in_.i1 * 32 + lane);
        g2 = __ldg(w2 + (size_t)in_.i2 * 32 + lane);
        g3 = __ldg(w3 + (size_t)in_.i3 * 32 + lane);

        in_ = inn;
    }
}

extern "C" void kernel_launch(void* const* d_in, const int* in_sizes, int n_in,
                              void* d_out, int out_size)
{
    const int*    obs0 = (const int*)d_in[0];
    const int*    obs1 = (const int*)d_in[1];
    const int*    act0 = (const int*)d_in[2];
    const int*    act1 = (const int*)d_in[3];
    const float4* w0   = (const float4*)d_in[4];
    const float4* w1   = (const float4*)d_in[5];
    const float4* w2   = (const float4*)d_in[6];
    const float4* w3   = (const float4*)d_in[7];
    const float4* bias = (const float4*)d_in[8];
    float4*       out  = (float4*)d_out;

    const int n = in_sizes[0];     // number of rows (N)
    const dim3 block(256);         // 8 warps/block
    const dim3 grid(148 * 5);      // one exact wave at 5 blocks/SM

    // L2 access-policy window over w_state0 (the biggest read-miss source).
    int maxWin = 0;
    cudaDeviceGetAttribute(&maxWin, cudaDevAttrMaxAccessPolicyWindowSize, 0);

    const size_t w0Bytes = (size_t)in_sizes[4] * sizeof(float);

    if (maxWin > 0) {
        cudaLaunchConfig_t cfg = {};
        cfg.gridDim  = grid;
        cfg.blockDim = block;
        cfg.dynamicSmemBytes = 0;
        cfg.stream = 0;   // same (default) stream the harness captures

        cudaLaunchAttribute attrs[1];
        attrs[0].id = cudaLaunchAttributeAccessPolicyWindow;
        attrs[0].val.accessPolicyWindow.base_ptr  = (void*)w0;
        attrs[0].val.accessPolicyWindow.num_bytes =
            w0Bytes < (size_t)maxWin ? w0Bytes : (size_t)maxWin;
        attrs[0].val.accessPolicyWindow.hitRatio  = 1.0f;
        attrs[0].val.accessPolicyWindow.hitProp   = cudaAccessPropertyPersisting;
        attrs[0].val.accessPolicyWindow.missProp  = cudaAccessPropertyStreaming;
        cfg.attrs    = attrs;
        cfg.numAttrs = 1;

        cudaLaunchKernelEx(&cfg, policy_encoder_kernel,
                           obs0, obs1, act0, act1,
                           w0, w1, w2, w3, bias, out, n);
    } else {
        policy_encoder_kernel<<<grid, block>>>(obs0, obs1, act0, act1,
                                               w0, w1, w2, w3, bias, out, n);
    }
}